// round 14
// baseline (speedup 1.0000x reference)
#include <cuda_runtime.h>

typedef unsigned long long u64;

#define D      32
#define KNN    4
#define NF     2048
#define NSMP   16384
#define WARPS  6
#define SPB    64        // samples per phase-A block; lane owns (lane, lane+32)
#define TILE   32
#define SPLIT  8         // max apply blocks per center

// ---------------- packed f32x2 helpers (sm_103a FFMA2 path) ----------------
__device__ __forceinline__ u64 fma2(u64 a, u64 b, u64 c) {
    u64 r;
    asm("fma.rn.f32x2 %0, %1, %2, %3;" : "=l"(r) : "l"(a), "l"(b), "l"(c));
    return r;
}
__device__ __forceinline__ u64 add2(u64 a, u64 b) {
    u64 r;
    asm("add.rn.f32x2 %0, %1, %2;" : "=l"(r) : "l"(a), "l"(b));
    return r;
}
__device__ __forceinline__ void unpack2(u64 a, float& lo, float& hi) {
    asm("mov.b64 {%0, %1}, %2;" : "=f"(lo), "=f"(hi) : "l"(a));
}
__device__ __forceinline__ u64 pack2(float a, float b) {
    u64 r;
    asm("mov.b64 %0, {%1, %2};" : "=l"(r) : "f"(a), "f"(b));
    return r;
}

// ---------------- device scratch (exact CSR, cannot overflow) ----------------
__device__ float g_cnorm[NF];
__device__ int   g_cnt[NF];
__device__ int   g_off[NF];
__device__ int   g_fill[NF];
__device__ int   g_cursor;
__device__ int   g_sel[NSMP * KNN];
__device__ int   g_bins[NSMP * KNN];

// ---------------- zero outputs + counters ----------------
__global__ void zero_kernel(float* __restrict__ y, int n_out, int n_fcns) {
    int i = blockIdx.x * blockDim.x + threadIdx.x;
    if (i < n_out) y[i] = 0.0f;
    if (i < n_fcns) { g_cnt[i] = 0; g_fill[i] = 0; }
    if (i == 0) g_cursor = 0;
}

// ---------------- per-center squared norms ----------------
__global__ void cnorm_kernel(const float* __restrict__ ctrs, int n_fcns) {
    int f = blockIdx.x * blockDim.x + threadIdx.x;
    if (f < n_fcns) {
        const float4* c4 = (const float4*)(ctrs + (size_t)f * D);
        float s = 0.0f;
#pragma unroll
        for (int j = 0; j < D / 4; j++) {
            float4 q = __ldg(c4 + j);
            s += q.x * q.x + q.y * q.y + q.z * q.z + q.w * q.w;
        }
        g_cnorm[f] = s;
    }
}

// select-only stable top-4 insert; SAFE when sc >= d3 (no-op). Strict <.
#define INS4(sc, f, d0, d1, d2, d3, i0, i1, i2, i3) do {                        \
    bool h0 = (sc) < d0, h1 = (sc) < d1, h2 = (sc) < d2, h3 = (sc) < d3;        \
    float n3 = h3 ? (h2 ? d2 : (sc)) : d3;  int m3 = h3 ? (h2 ? i2 : (f)) : i3; \
    float n2 = h2 ? (h1 ? d1 : (sc)) : d2;  int m2 = h2 ? (h1 ? i1 : (f)) : i2; \
    float n1 = h1 ? (h0 ? d0 : (sc)) : d1;  int m1 = h1 ? (h0 ? i0 : (f)) : i1; \
    d0 = h0 ? (sc) : d0;                    i0 = h0 ? (f) : i0;                 \
    d1 = n1; i1 = m1; d2 = n2; i2 = m2; d3 = n3; i3 = m3;                       \
} while (0)

// ---------------- phase A: top-4 selection, per-sample winners + counts ----
// Block = 192 threads = 6 warps, 64 samples. Lane owns samples lane & lane+32,
// so every center broadcast (8x LDS.128 + cnorm) serves 64 sample-pairs.
// Warp w scans a tile-granular shard (11/11/11/11/10/10 tiles of 32). Merge
// 24 -> 4 per sample -> g_sel + g_cnt.
__global__ __launch_bounds__(192, 2) void pwlA_kernel(
    const float* __restrict__ x,
    const float* __restrict__ ctrs,
    int n_fcns)
{
    __shared__ __align__(16) float s_ctr[WARPS][TILE * D];   // 24 KB
    __shared__ float s_cn[WARPS][TILE];
    __shared__ float s_cd[SPB][WARPS * KNN];
    __shared__ int   s_ci[SPB][WARPS * KNN];

    const int lane = threadIdx.x & 31;
    const int w    = threadIdx.x >> 5;
    const int rowA = blockIdx.x * SPB + lane;
    const int rowB = rowA + 32;

    // ---- load both sample rows as packed (-2*x) ----
    u64 xpA[16], xpB[16];
    {
        const float4* ga = (const float4*)(x + (size_t)rowA * D);
        const float4* gb = (const float4*)(x + (size_t)rowB * D);
#pragma unroll
        for (int j = 0; j < 8; j++) {
            float4 qa = __ldg(ga + j);
            float4 qb = __ldg(gb + j);
            xpA[2 * j]     = pack2(-2.0f * qa.x, -2.0f * qa.y);
            xpA[2 * j + 1] = pack2(-2.0f * qa.z, -2.0f * qa.w);
            xpB[2 * j]     = pack2(-2.0f * qb.x, -2.0f * qb.y);
            xpB[2 * j + 1] = pack2(-2.0f * qb.z, -2.0f * qb.w);
        }
    }

    // ---- tile-granular shard: warps 0-3 get 11 tiles, warps 4-5 get 10 ----
    const int tb = (w < 4) ? w * 11 : 44 + (w - 4) * 10;
    const int te = tb + ((w < 4) ? 11 : 10);

    float A0 = 3.4e38f, A1 = 3.4e38f, A2 = 3.4e38f, A3 = 3.4e38f;
    float B0 = 3.4e38f, B1 = 3.4e38f, B2 = 3.4e38f, B3 = 3.4e38f;
    int   Ai0 = 0, Ai1 = 0, Ai2 = 0, Ai3 = 0;
    int   Bi0 = 0, Bi1 = 0, Bi2 = 0, Bi3 = 0;

    const float4* cg4 = (const float4*)ctrs;

    for (int tt = tb; tt < te; tt++) {
        const int t = tt * TILE;
        __syncwarp();
        // stage 32 centers for this warp (exact tiles, no guards)
#pragma unroll
        for (int i = 0; i < 8; i++) {
            int e = i * 32 + lane;                             // 0..255
            ((float4*)s_ctr[w])[e] = __ldg(cg4 + (size_t)(t + (e >> 3)) * 8 + (e & 7));
        }
        s_cn[w][lane] = g_cnorm[t + lane];
        __syncwarp();

#pragma unroll 2
        for (int ff = 0; ff < TILE; ff++) {
            const ulonglong2* c2 = (const ulonglong2*)(s_ctr[w] + ff * D);
            u64 cnp = (u64)__float_as_uint(s_cn[w][ff]);       // (cnorm, 0)
            u64 a0 = 0ull, a1 = 0ull, a2 = 0ull, a3 = cnp;
            u64 b0 = 0ull, b1 = 0ull, b2 = 0ull, b3 = cnp;
#pragma unroll
            for (int j = 0; j < 4; j++) {
                ulonglong2 qa = c2[2 * j];
                ulonglong2 qb = c2[2 * j + 1];
                a0 = fma2(xpA[4 * j + 0], qa.x, a0);
                b0 = fma2(xpB[4 * j + 0], qa.x, b0);
                a1 = fma2(xpA[4 * j + 1], qa.y, a1);
                b1 = fma2(xpB[4 * j + 1], qa.y, b1);
                a2 = fma2(xpA[4 * j + 2], qb.x, a2);
                b2 = fma2(xpB[4 * j + 2], qb.x, b2);
                a3 = fma2(xpA[4 * j + 3], qb.y, a3);
                b3 = fma2(xpB[4 * j + 3], qb.y, b3);
            }
            u64 ra = add2(add2(a0, a1), add2(a2, a3));
            u64 rb = add2(add2(b0, b1), add2(b2, b3));
            float la, ha, lb, hb;
            unpack2(ra, la, ha);
            unpack2(rb, lb, hb);
            float scA = la + ha;               // == cnorm - 2*dot (rank-equiv)
            float scB = lb + hb;
            const int f = t + ff;
            if (scA < A3 || scB < B3) {        // rare after warmup
                INS4(scA, f, A0, A1, A2, A3, Ai0, Ai1, Ai2, Ai3);
                INS4(scB, f, B0, B1, B2, B3, Bi0, Bi1, Bi2, Bi3);
            }
        }
    }

    // ---- publish candidates (24 per sample) ----
    s_cd[lane][w * KNN + 0] = A0;       s_ci[lane][w * KNN + 0] = Ai0;
    s_cd[lane][w * KNN + 1] = A1;       s_ci[lane][w * KNN + 1] = Ai1;
    s_cd[lane][w * KNN + 2] = A2;       s_ci[lane][w * KNN + 2] = Ai2;
    s_cd[lane][w * KNN + 3] = A3;       s_ci[lane][w * KNN + 3] = Ai3;
    s_cd[lane + 32][w * KNN + 0] = B0;  s_ci[lane + 32][w * KNN + 0] = Bi0;
    s_cd[lane + 32][w * KNN + 1] = B1;  s_ci[lane + 32][w * KNN + 1] = Bi1;
    s_cd[lane + 32][w * KNN + 2] = B2;  s_ci[lane + 32][w * KNN + 2] = Bi2;
    s_cd[lane + 32][w * KNN + 3] = B3;  s_ci[lane + 32][w * KNN + 3] = Bi3;
    __syncthreads();

    // ---- merge 24 -> 4 per sample; record winners + counts ----
    if (threadIdx.x < SPB) {
        const int ms = threadIdx.x;
        const int n  = blockIdx.x * SPB + ms;
        float cd[WARPS * KNN];
        int   ci[WARPS * KNN];
#pragma unroll
        for (int j = 0; j < WARPS * KNN; j++) {
            cd[j] = s_cd[ms][j];
            ci[j] = s_ci[ms][j];
        }
#pragma unroll
        for (int k = 0; k < KNN; k++) {
            int best = 0;
#pragma unroll
            for (int j = 1; j < WARPS * KNN; j++) {
                // lexicographic (dist, idx): matches top_k tie-break
                if (cd[j] < cd[best] || (cd[j] == cd[best] && ci[j] < ci[best]))
                    best = j;
            }
            int f = ci[best];
            cd[best] = 3.4e38f;
            g_sel[n * KNN + k] = f;
            atomicAdd(&g_cnt[f], 1);
        }
    }
}

// ---------------- offsets via atomic cursor (bin order is irrelevant) ------
__global__ void offsets_kernel(int n_fcns) {
    int f = blockIdx.x * blockDim.x + threadIdx.x;
    if (f < n_fcns) g_off[f] = atomicAdd(&g_cursor, g_cnt[f]);
}

// ---------------- fill CSR bins ----------------
__global__ void fill_kernel(int total) {
    int i = blockIdx.x * blockDim.x + threadIdx.x;
    if (i < total) {
        int f = g_sel[i];
        int pos = atomicAdd(&g_fill[f], 1);
        g_bins[g_off[f] + pos] = i >> 2;    // sample id
    }
}

// ---------------- phase B: center-major apply ----------------
// Blocks (f, s): W_f/c_f/off_f staged once per surviving block; large bins
// split across up to SPLIT blocks (chunk >= 64; extras exit before W load).
__global__ __launch_bounds__(256) void apply_kernel(
    const float* __restrict__ x,
    const float* __restrict__ ctrs,
    const float* __restrict__ wts,
    const float* __restrict__ offs,
    float* __restrict__ y)
{
    const int f   = blockIdx.x;
    const int cnt = g_cnt[f];
    if (cnt == 0) return;
    const int chunk = max(64, (cnt + SPLIT - 1) / SPLIT);
    const int start = blockIdx.y * chunk;
    if (start >= cnt) return;
    const int end = min(cnt, start + chunk);
    const int b0  = g_off[f];

    __shared__ float sW[D * D];
    __shared__ float sc[D];
    __shared__ float so[D];

    const int tid  = threadIdx.x;
    const int lane = tid & 31;
    const int w    = tid >> 5;

    ((float4*)sW)[tid] = __ldg((const float4*)(wts + (size_t)f * D * D) + tid);
    if (tid < D) {
        sc[tid] = __ldg(ctrs + (size_t)f * D + tid);
        so[tid] = __ldg(offs + (size_t)f * D + tid);
    }
    __syncthreads();

    // per-warp contiguous sub-range, 2 samples in flight
    const int len = end - start;
    const int per = (len + 7) / 8;
    int i  = start + w * per;
    int we = min(end, i + per);

    for (; i + 1 < we; i += 2) {
        const int n0 = g_bins[b0 + i];
        const int n1 = g_bins[b0 + i + 1];
        const float4* x0 = (const float4*)(x + (size_t)n0 * D);
        const float4* x1 = (const float4*)(x + (size_t)n1 * D);
        float a0 = so[lane], a1 = 0.0f;
        float c0 = so[lane], c1 = 0.0f;
#pragma unroll
        for (int j = 0; j < 8; j++) {
            float4 q0 = __ldg(x0 + j);
            float4 q1 = __ldg(x1 + j);
            a0 = fmaf(q0.x - sc[4 * j + 0], sW[(4 * j + 0) * D + lane], a0);
            c0 = fmaf(q1.x - sc[4 * j + 0], sW[(4 * j + 0) * D + lane], c0);
            a1 = fmaf(q0.y - sc[4 * j + 1], sW[(4 * j + 1) * D + lane], a1);
            c1 = fmaf(q1.y - sc[4 * j + 1], sW[(4 * j + 1) * D + lane], c1);
            a0 = fmaf(q0.z - sc[4 * j + 2], sW[(4 * j + 2) * D + lane], a0);
            c0 = fmaf(q1.z - sc[4 * j + 2], sW[(4 * j + 2) * D + lane], c0);
            a1 = fmaf(q0.w - sc[4 * j + 3], sW[(4 * j + 3) * D + lane], a1);
            c1 = fmaf(q1.w - sc[4 * j + 3], sW[(4 * j + 3) * D + lane], c1);
        }
        atomicAdd(y + (size_t)n0 * D + lane, a0 + a1);
        atomicAdd(y + (size_t)n1 * D + lane, c0 + c1);
    }
    if (i < we) {
        const int n0 = g_bins[b0 + i];
        const float4* x0 = (const float4*)(x + (size_t)n0 * D);
        float a0 = so[lane], a1 = 0.0f;
#pragma unroll
        for (int j = 0; j < 8; j++) {
            float4 q0 = __ldg(x0 + j);
            a0 = fmaf(q0.x - sc[4 * j + 0], sW[(4 * j + 0) * D + lane], a0);
            a1 = fmaf(q0.y - sc[4 * j + 1], sW[(4 * j + 1) * D + lane], a1);
            a0 = fmaf(q0.z - sc[4 * j + 2], sW[(4 * j + 2) * D + lane], a0);
            a1 = fmaf(q0.w - sc[4 * j + 3], sW[(4 * j + 3) * D + lane], a1);
        }
        atomicAdd(y + (size_t)n0 * D + lane, a0 + a1);
    }
}

// ---------------- launch ----------------
extern "C" void kernel_launch(void* const* d_in, const int* in_sizes, int n_in,
                              void* d_out, int out_size)
{
    const float* x    = (const float*)d_in[0];
    const float* ctrs = (const float*)d_in[1];
    const float* wts  = (const float*)d_in[2];
    const float* offs = (const float*)d_in[3];
    float* y = (float*)d_out;

    int n_smps = in_sizes[0] / D;
    int n_fcns = in_sizes[1] / D;

    zero_kernel<<<(out_size + 255) / 256, 256>>>(y, out_size, n_fcns);
    cnorm_kernel<<<(n_fcns + 255) / 256, 256>>>(ctrs, n_fcns);
    pwlA_kernel<<<n_smps / SPB, 192>>>(x, ctrs, n_fcns);
    offsets_kernel<<<(n_fcns + 255) / 256, 256>>>(n_fcns);
    fill_kernel<<<(n_smps * KNN + 255) / 256, 256>>>(n_smps * KNN);
    dim3 agrid(n_fcns, SPLIT);
    apply_kernel<<<agrid, 256>>>(x, ctrs, wts, offs, y);
}

// round 15
// speedup vs baseline: 1.0644x; 1.0644x over previous
#include <cuda_runtime.h>

typedef unsigned long long u64;

#define D      32
#define KNN    4
#define NF     2048
#define NSMP   16384
#define WARPS  6
#define SPB    64        // samples per phase-A block; lane owns (lane, lane+32)
#define TILE   32
#define SPLIT  8         // max apply blocks per center

// ---------------- packed f32x2 helpers (sm_103a FFMA2 path) ----------------
__device__ __forceinline__ u64 fma2(u64 a, u64 b, u64 c) {
    u64 r;
    asm("fma.rn.f32x2 %0, %1, %2, %3;" : "=l"(r) : "l"(a), "l"(b), "l"(c));
    return r;
}
__device__ __forceinline__ u64 add2(u64 a, u64 b) {
    u64 r;
    asm("add.rn.f32x2 %0, %1, %2;" : "=l"(r) : "l"(a), "l"(b));
    return r;
}
__device__ __forceinline__ void unpack2(u64 a, float& lo, float& hi) {
    asm("mov.b64 {%0, %1}, %2;" : "=f"(lo), "=f"(hi) : "l"(a));
}
__device__ __forceinline__ u64 pack2(float a, float b) {
    u64 r;
    asm("mov.b64 %0, {%1, %2};" : "=l"(r) : "f"(a), "f"(b));
    return r;
}

// ---------------- device scratch ----------------
// g_bins stride = NSMP: a center can be selected at most once per sample,
// so overflow is structurally impossible. 128MB static scratch (allowed).
__device__ float g_cnorm[NF];
__device__ int   g_cnt[NF];
__device__ int   g_bins[(size_t)NF * NSMP];

// ---------------- prep: zero y + counters, compute cnorm (ONE kernel) ------
__global__ void prep_kernel(float* __restrict__ y, int n_out,
                            const float* __restrict__ ctrs, int n_fcns) {
    int i = blockIdx.x * blockDim.x + threadIdx.x;
    if (i < n_out) y[i] = 0.0f;
    if (i < n_fcns) {
        g_cnt[i] = 0;
        const float4* c4 = (const float4*)(ctrs + (size_t)i * D);
        float s = 0.0f;
#pragma unroll
        for (int j = 0; j < D / 4; j++) {
            float4 q = __ldg(c4 + j);
            s += q.x * q.x + q.y * q.y + q.z * q.z + q.w * q.w;
        }
        g_cnorm[i] = s;
    }
}

// select-only stable top-4 insert; SAFE when sc >= d3 (no-op). Strict <.
#define INS4(sc, f, d0, d1, d2, d3, i0, i1, i2, i3) do {                        \
    bool h0 = (sc) < d0, h1 = (sc) < d1, h2 = (sc) < d2, h3 = (sc) < d3;        \
    float n3 = h3 ? (h2 ? d2 : (sc)) : d3;  int m3 = h3 ? (h2 ? i2 : (f)) : i3; \
    float n2 = h2 ? (h1 ? d1 : (sc)) : d2;  int m2 = h2 ? (h1 ? i1 : (f)) : i2; \
    float n1 = h1 ? (h0 ? d0 : (sc)) : d1;  int m1 = h1 ? (h0 ? i0 : (f)) : i1; \
    d0 = h0 ? (sc) : d0;                    i0 = h0 ? (f) : i0;                 \
    d1 = n1; i1 = m1; d2 = n2; i2 = m2; d3 = n3; i3 = m3;                       \
} while (0)

// ---------------- phase A: top-4 selection + direct binning ----------------
// Block = 192 threads = 6 warps, 64 samples. Lane owns samples lane & lane+32,
// so every center broadcast (8x LDS.128 + cnorm) serves 64 sample-pairs.
// Warp w scans a tile-granular shard (11/11/11/11/10/10 tiles of 32). Merge
// 24 -> 4 per sample; winners scattered straight into per-center bins.
__global__ __launch_bounds__(192, 2) void pwlA_kernel(
    const float* __restrict__ x,
    const float* __restrict__ ctrs,
    int n_fcns)
{
    __shared__ __align__(16) float s_ctr[WARPS][TILE * D];   // 24 KB
    __shared__ float s_cn[WARPS][TILE];
    __shared__ float s_cd[SPB][WARPS * KNN];
    __shared__ int   s_ci[SPB][WARPS * KNN];

    const int lane = threadIdx.x & 31;
    const int w    = threadIdx.x >> 5;
    const int rowA = blockIdx.x * SPB + lane;
    const int rowB = rowA + 32;

    // ---- load both sample rows as packed (-2*x) ----
    u64 xpA[16], xpB[16];
    {
        const float4* ga = (const float4*)(x + (size_t)rowA * D);
        const float4* gb = (const float4*)(x + (size_t)rowB * D);
#pragma unroll
        for (int j = 0; j < 8; j++) {
            float4 qa = __ldg(ga + j);
            float4 qb = __ldg(gb + j);
            xpA[2 * j]     = pack2(-2.0f * qa.x, -2.0f * qa.y);
            xpA[2 * j + 1] = pack2(-2.0f * qa.z, -2.0f * qa.w);
            xpB[2 * j]     = pack2(-2.0f * qb.x, -2.0f * qb.y);
            xpB[2 * j + 1] = pack2(-2.0f * qb.z, -2.0f * qb.w);
        }
    }

    // ---- tile-granular shard: warps 0-3 get 11 tiles, warps 4-5 get 10 ----
    const int tb = (w < 4) ? w * 11 : 44 + (w - 4) * 10;
    const int te = tb + ((w < 4) ? 11 : 10);

    float A0 = 3.4e38f, A1 = 3.4e38f, A2 = 3.4e38f, A3 = 3.4e38f;
    float B0 = 3.4e38f, B1 = 3.4e38f, B2 = 3.4e38f, B3 = 3.4e38f;
    int   Ai0 = 0, Ai1 = 0, Ai2 = 0, Ai3 = 0;
    int   Bi0 = 0, Bi1 = 0, Bi2 = 0, Bi3 = 0;

    const float4* cg4 = (const float4*)ctrs;

    for (int tt = tb; tt < te; tt++) {
        const int t = tt * TILE;
        __syncwarp();
        // stage 32 centers for this warp (exact tiles, no guards)
#pragma unroll
        for (int i = 0; i < 8; i++) {
            int e = i * 32 + lane;                             // 0..255
            ((float4*)s_ctr[w])[e] = __ldg(cg4 + (size_t)(t + (e >> 3)) * 8 + (e & 7));
        }
        s_cn[w][lane] = g_cnorm[t + lane];
        __syncwarp();

#pragma unroll 2
        for (int ff = 0; ff < TILE; ff++) {
            const ulonglong2* c2 = (const ulonglong2*)(s_ctr[w] + ff * D);
            u64 cnp = (u64)__float_as_uint(s_cn[w][ff]);       // (cnorm, 0)
            u64 a0 = 0ull, a1 = 0ull, a2 = 0ull, a3 = cnp;
            u64 b0 = 0ull, b1 = 0ull, b2 = 0ull, b3 = cnp;
#pragma unroll
            for (int j = 0; j < 4; j++) {
                ulonglong2 qa = c2[2 * j];
                ulonglong2 qb = c2[2 * j + 1];
                a0 = fma2(xpA[4 * j + 0], qa.x, a0);
                b0 = fma2(xpB[4 * j + 0], qa.x, b0);
                a1 = fma2(xpA[4 * j + 1], qa.y, a1);
                b1 = fma2(xpB[4 * j + 1], qa.y, b1);
                a2 = fma2(xpA[4 * j + 2], qb.x, a2);
                b2 = fma2(xpB[4 * j + 2], qb.x, b2);
                a3 = fma2(xpA[4 * j + 3], qb.y, a3);
                b3 = fma2(xpB[4 * j + 3], qb.y, b3);
            }
            u64 ra = add2(add2(a0, a1), add2(a2, a3));
            u64 rb = add2(add2(b0, b1), add2(b2, b3));
            float la, ha, lb, hb;
            unpack2(ra, la, ha);
            unpack2(rb, lb, hb);
            float scA = la + ha;               // == cnorm - 2*dot (rank-equiv)
            float scB = lb + hb;
            const int f = t + ff;
            if (scA < A3 || scB < B3) {        // rare after warmup
                INS4(scA, f, A0, A1, A2, A3, Ai0, Ai1, Ai2, Ai3);
                INS4(scB, f, B0, B1, B2, B3, Bi0, Bi1, Bi2, Bi3);
            }
        }
    }

    // ---- publish candidates (24 per sample) ----
    s_cd[lane][w * KNN + 0] = A0;       s_ci[lane][w * KNN + 0] = Ai0;
    s_cd[lane][w * KNN + 1] = A1;       s_ci[lane][w * KNN + 1] = Ai1;
    s_cd[lane][w * KNN + 2] = A2;       s_ci[lane][w * KNN + 2] = Ai2;
    s_cd[lane][w * KNN + 3] = A3;       s_ci[lane][w * KNN + 3] = Ai3;
    s_cd[lane + 32][w * KNN + 0] = B0;  s_ci[lane + 32][w * KNN + 0] = Bi0;
    s_cd[lane + 32][w * KNN + 1] = B1;  s_ci[lane + 32][w * KNN + 1] = Bi1;
    s_cd[lane + 32][w * KNN + 2] = B2;  s_ci[lane + 32][w * KNN + 2] = Bi2;
    s_cd[lane + 32][w * KNN + 3] = B3;  s_ci[lane + 32][w * KNN + 3] = Bi3;
    __syncthreads();

    // ---- merge 24 -> 4 per sample; scatter straight into bins ----
    if (threadIdx.x < SPB) {
        const int ms = threadIdx.x;
        const int n  = blockIdx.x * SPB + ms;
        float cd[WARPS * KNN];
        int   ci[WARPS * KNN];
#pragma unroll
        for (int j = 0; j < WARPS * KNN; j++) {
            cd[j] = s_cd[ms][j];
            ci[j] = s_ci[ms][j];
        }
#pragma unroll
        for (int k = 0; k < KNN; k++) {
            int best = 0;
#pragma unroll
            for (int j = 1; j < WARPS * KNN; j++) {
                // lexicographic (dist, idx): matches top_k tie-break
                if (cd[j] < cd[best] || (cd[j] == cd[best] && ci[j] < ci[best]))
                    best = j;
            }
            int f = ci[best];
            cd[best] = 3.4e38f;
            int pos = atomicAdd(&g_cnt[f], 1);
            g_bins[(size_t)f * NSMP + pos] = n;
        }
    }
}

// ---------------- phase B: center-major apply ----------------
// Blocks (f, s): W_f/c_f/off_f staged once per surviving block; large bins
// split across up to SPLIT blocks (chunk >= 64; extras exit before W load).
__global__ __launch_bounds__(256) void apply_kernel(
    const float* __restrict__ x,
    const float* __restrict__ ctrs,
    const float* __restrict__ wts,
    const float* __restrict__ offs,
    float* __restrict__ y)
{
    const int f   = blockIdx.x;
    const int cnt = g_cnt[f];
    if (cnt == 0) return;
    const int chunk = max(64, (cnt + SPLIT - 1) / SPLIT);
    const int start = blockIdx.y * chunk;
    if (start >= cnt) return;
    const int end = min(cnt, start + chunk);
    const int* bin = g_bins + (size_t)f * NSMP;

    __shared__ float sW[D * D];
    __shared__ float sc[D];
    __shared__ float so[D];

    const int tid  = threadIdx.x;
    const int lane = tid & 31;
    const int w    = tid >> 5;

    ((float4*)sW)[tid] = __ldg((const float4*)(wts + (size_t)f * D * D) + tid);
    if (tid < D) {
        sc[tid] = __ldg(ctrs + (size_t)f * D + tid);
        so[tid] = __ldg(offs + (size_t)f * D + tid);
    }
    __syncthreads();

    // per-warp contiguous sub-range, 2 samples in flight
    const int len = end - start;
    const int per = (len + 7) / 8;
    int i  = start + w * per;
    int we = min(end, i + per);

    for (; i + 1 < we; i += 2) {
        const int n0 = bin[i];
        const int n1 = bin[i + 1];
        const float4* x0 = (const float4*)(x + (size_t)n0 * D);
        const float4* x1 = (const float4*)(x + (size_t)n1 * D);
        float a0 = so[lane], a1 = 0.0f;
        float c0 = so[lane], c1 = 0.0f;
#pragma unroll
        for (int j = 0; j < 8; j++) {
            float4 q0 = __ldg(x0 + j);
            float4 q1 = __ldg(x1 + j);
            a0 = fmaf(q0.x - sc[4 * j + 0], sW[(4 * j + 0) * D + lane], a0);
            c0 = fmaf(q1.x - sc[4 * j + 0], sW[(4 * j + 0) * D + lane], c0);
            a1 = fmaf(q0.y - sc[4 * j + 1], sW[(4 * j + 1) * D + lane], a1);
            c1 = fmaf(q1.y - sc[4 * j + 1], sW[(4 * j + 1) * D + lane], c1);
            a0 = fmaf(q0.z - sc[4 * j + 2], sW[(4 * j + 2) * D + lane], a0);
            c0 = fmaf(q1.z - sc[4 * j + 2], sW[(4 * j + 2) * D + lane], c0);
            a1 = fmaf(q0.w - sc[4 * j + 3], sW[(4 * j + 3) * D + lane], a1);
            c1 = fmaf(q1.w - sc[4 * j + 3], sW[(4 * j + 3) * D + lane], c1);
        }
        atomicAdd(y + (size_t)n0 * D + lane, a0 + a1);
        atomicAdd(y + (size_t)n1 * D + lane, c0 + c1);
    }
    if (i < we) {
        const int n0 = bin[i];
        const float4* x0 = (const float4*)(x + (size_t)n0 * D);
        float a0 = so[lane], a1 = 0.0f;
#pragma unroll
        for (int j = 0; j < 8; j++) {
            float4 q0 = __ldg(x0 + j);
            a0 = fmaf(q0.x - sc[4 * j + 0], sW[(4 * j + 0) * D + lane], a0);
            a1 = fmaf(q0.y - sc[4 * j + 1], sW[(4 * j + 1) * D + lane], a1);
            a0 = fmaf(q0.z - sc[4 * j + 2], sW[(4 * j + 2) * D + lane], a0);
            a1 = fmaf(q0.w - sc[4 * j + 3], sW[(4 * j + 3) * D + lane], a1);
        }
        atomicAdd(y + (size_t)n0 * D + lane, a0 + a1);
    }
}

// ---------------- launch (3 kernels total) ----------------
extern "C" void kernel_launch(void* const* d_in, const int* in_sizes, int n_in,
                              void* d_out, int out_size)
{
    const float* x    = (const float*)d_in[0];
    const float* ctrs = (const float*)d_in[1];
    const float* wts  = (const float*)d_in[2];
    const float* offs = (const float*)d_in[3];
    float* y = (float*)d_out;

    int n_smps = in_sizes[0] / D;
    int n_fcns = in_sizes[1] / D;

    prep_kernel<<<(out_size + 255) / 256, 256>>>(y, out_size, ctrs, n_fcns);
    pwlA_kernel<<<n_smps / SPB, 192>>>(x, ctrs, n_fcns);
    dim3 agrid(n_fcns, SPLIT);
    apply_kernel<<<agrid, 256>>>(x, ctrs, wts, offs, y);
}

// round 16
// speedup vs baseline: 1.2054x; 1.1324x over previous
#include <cuda_runtime.h>

typedef unsigned long long u64;

#define D      32
#define KNN    4
#define WARPS  6
#define SPB    64        // samples per block; lane owns (lane, lane+32)
#define TILE   32

// ---------------- packed f32x2 helpers (sm_103a FFMA2 path) ----------------
__device__ __forceinline__ u64 fma2(u64 a, u64 b, u64 c) {
    u64 r;
    asm("fma.rn.f32x2 %0, %1, %2, %3;" : "=l"(r) : "l"(a), "l"(b), "l"(c));
    return r;
}
__device__ __forceinline__ u64 add2(u64 a, u64 b) {
    u64 r;
    asm("add.rn.f32x2 %0, %1, %2;" : "=l"(r) : "l"(a), "l"(b));
    return r;
}
__device__ __forceinline__ void unpack2(u64 a, float& lo, float& hi) {
    asm("mov.b64 {%0, %1}, %2;" : "=f"(lo), "=f"(hi) : "l"(a));
}
__device__ __forceinline__ u64 pack2(float a, float b) {
    u64 r;
    asm("mov.b64 %0, {%1, %2};" : "=l"(r) : "f"(a), "f"(b));
    return r;
}

// select-only stable top-4 insert; SAFE when sc >= d3 (no-op). Strict <.
#define INS4(sc, f, d0, d1, d2, d3, i0, i1, i2, i3) do {                        \
    bool h0 = (sc) < d0, h1 = (sc) < d1, h2 = (sc) < d2, h3 = (sc) < d3;        \
    float n3 = h3 ? (h2 ? d2 : (sc)) : d3;  int m3 = h3 ? (h2 ? i2 : (f)) : i3; \
    float n2 = h2 ? (h1 ? d1 : (sc)) : d2;  int m2 = h2 ? (h1 ? i1 : (f)) : i2; \
    float n1 = h1 ? (h0 ? d0 : (sc)) : d1;  int m1 = h1 ? (h0 ? i0 : (f)) : i1; \
    d0 = h0 ? (sc) : d0;                    i0 = h0 ? (f) : i0;                 \
    d1 = n1; i1 = m1; d2 = n2; i2 = m2; d3 = n3; i3 = m3;                       \
} while (0)

// ---------------- single fused kernel ----------------
// Block = 192 threads = 6 warps, 64 samples. Lane owns samples lane & lane+32,
// so every center broadcast (8x LDS.128 + cnorm) serves 64 sample-pairs.
// Center norms are computed INLINE during tile staging via shfl butterfly
// (no prep kernel, no global round-trip). Warp w scans a tile-granular shard
// (11/11/11/11/10/10 tiles of 32). Merge 24 -> 4 per sample, then the
// warp-cooperative apply writes y directly. ONE kernel, ONE graph node.
__global__ __launch_bounds__(192, 2) void pwl_kernel(
    const float* __restrict__ x,
    const float* __restrict__ ctrs,
    const float* __restrict__ wts,
    const float* __restrict__ offs,
    float* __restrict__ y,
    int n_fcns)
{
    __shared__ __align__(16) float s_ctr[WARPS][TILE * D];   // 24 KB
    __shared__ float s_cn[WARPS][TILE];
    __shared__ float s_x[SPB * (D + 1)];
    __shared__ float s_cd[SPB][WARPS * KNN];
    __shared__ int   s_ci[SPB][WARPS * KNN];
    __shared__ int   s_idx[SPB][KNN];

    const int lane = threadIdx.x & 31;
    const int w    = threadIdx.x >> 5;
    const int rowA = blockIdx.x * SPB + lane;
    const int rowB = rowA + 32;

    // ---- load both sample rows: registers hold packed (-2*x); warp 0 -> smem ----
    u64 xpA[16], xpB[16];
    {
        const float4* ga = (const float4*)(x + (size_t)rowA * D);
        const float4* gb = (const float4*)(x + (size_t)rowB * D);
#pragma unroll
        for (int j = 0; j < 8; j++) {
            float4 qa = __ldg(ga + j);
            float4 qb = __ldg(gb + j);
            if (w == 0) {
                float* da = s_x + lane * (D + 1) + 4 * j;
                float* db = s_x + (lane + 32) * (D + 1) + 4 * j;
                da[0] = qa.x; da[1] = qa.y; da[2] = qa.z; da[3] = qa.w;
                db[0] = qb.x; db[1] = qb.y; db[2] = qb.z; db[3] = qb.w;
            }
            xpA[2 * j]     = pack2(-2.0f * qa.x, -2.0f * qa.y);
            xpA[2 * j + 1] = pack2(-2.0f * qa.z, -2.0f * qa.w);
            xpB[2 * j]     = pack2(-2.0f * qb.x, -2.0f * qb.y);
            xpB[2 * j + 1] = pack2(-2.0f * qb.z, -2.0f * qb.w);
        }
    }

    // ---- tile-granular shard: warps 0-3 get 11 tiles, warps 4-5 get 10 ----
    const int tb = (w < 4) ? w * 11 : 44 + (w - 4) * 10;
    const int te = tb + ((w < 4) ? 11 : 10);

    float A0 = 3.4e38f, A1 = 3.4e38f, A2 = 3.4e38f, A3 = 3.4e38f;
    float B0 = 3.4e38f, B1 = 3.4e38f, B2 = 3.4e38f, B3 = 3.4e38f;
    int   Ai0 = 0, Ai1 = 0, Ai2 = 0, Ai3 = 0;
    int   Bi0 = 0, Bi1 = 0, Bi2 = 0, Bi3 = 0;

    const float4* cg4 = (const float4*)ctrs;

    for (int tt = tb; tt < te; tt++) {
        const int t = tt * TILE;
        __syncwarp();
        // stage 32 centers for this warp + inline cnorm via shfl butterfly.
        // e = i*32+lane: center t + i*4 + (lane>>3), 16B-chunk (lane&7).
        // Lanes 8g..8g+7 hold the 8 chunks of one center -> reduce with
        // shfl_xor {1,2,4}; lane&7==0 writes s_cn.
#pragma unroll
        for (int i = 0; i < 8; i++) {
            int e = i * 32 + lane;                             // 0..255
            float4 q = __ldg(cg4 + (size_t)(t + (e >> 3)) * 8 + (e & 7));
            ((float4*)s_ctr[w])[e] = q;
            float p = q.x * q.x + q.y * q.y + q.z * q.z + q.w * q.w;
            p += __shfl_xor_sync(0xffffffffu, p, 1);
            p += __shfl_xor_sync(0xffffffffu, p, 2);
            p += __shfl_xor_sync(0xffffffffu, p, 4);
            if ((lane & 7) == 0)
                s_cn[w][i * 4 + (lane >> 3)] = p;
        }
        __syncwarp();

#pragma unroll 2
        for (int ff = 0; ff < TILE; ff++) {
            const ulonglong2* c2 = (const ulonglong2*)(s_ctr[w] + ff * D);
            u64 cnp = (u64)__float_as_uint(s_cn[w][ff]);       // (cnorm, 0)
            u64 a0 = 0ull, a1 = 0ull, a2 = 0ull, a3 = cnp;
            u64 b0 = 0ull, b1 = 0ull, b2 = 0ull, b3 = cnp;
#pragma unroll
            for (int j = 0; j < 4; j++) {
                ulonglong2 qa = c2[2 * j];
                ulonglong2 qb = c2[2 * j + 1];
                a0 = fma2(xpA[4 * j + 0], qa.x, a0);
                b0 = fma2(xpB[4 * j + 0], qa.x, b0);
                a1 = fma2(xpA[4 * j + 1], qa.y, a1);
                b1 = fma2(xpB[4 * j + 1], qa.y, b1);
                a2 = fma2(xpA[4 * j + 2], qb.x, a2);
                b2 = fma2(xpB[4 * j + 2], qb.x, b2);
                a3 = fma2(xpA[4 * j + 3], qb.y, a3);
                b3 = fma2(xpB[4 * j + 3], qb.y, b3);
            }
            u64 ra = add2(add2(a0, a1), add2(a2, a3));
            u64 rb = add2(add2(b0, b1), add2(b2, b3));
            float la, ha, lb, hb;
            unpack2(ra, la, ha);
            unpack2(rb, lb, hb);
            float scA = la + ha;               // == cnorm - 2*dot (rank-equiv)
            float scB = lb + hb;
            const int f = t + ff;
            if (scA < A3 || scB < B3) {        // rare after warmup
                INS4(scA, f, A0, A1, A2, A3, Ai0, Ai1, Ai2, Ai3);
                INS4(scB, f, B0, B1, B2, B3, Bi0, Bi1, Bi2, Bi3);
            }
        }
    }

    // ---- publish candidates, merge 24 -> 4 per sample ----
    s_cd[lane][w * KNN + 0] = A0;       s_ci[lane][w * KNN + 0] = Ai0;
    s_cd[lane][w * KNN + 1] = A1;       s_ci[lane][w * KNN + 1] = Ai1;
    s_cd[lane][w * KNN + 2] = A2;       s_ci[lane][w * KNN + 2] = Ai2;
    s_cd[lane][w * KNN + 3] = A3;       s_ci[lane][w * KNN + 3] = Ai3;
    s_cd[lane + 32][w * KNN + 0] = B0;  s_ci[lane + 32][w * KNN + 0] = Bi0;
    s_cd[lane + 32][w * KNN + 1] = B1;  s_ci[lane + 32][w * KNN + 1] = Bi1;
    s_cd[lane + 32][w * KNN + 2] = B2;  s_ci[lane + 32][w * KNN + 2] = Bi2;
    s_cd[lane + 32][w * KNN + 3] = B3;  s_ci[lane + 32][w * KNN + 3] = Bi3;
    __syncthreads();

    if (threadIdx.x < SPB) {
        const int ms = threadIdx.x;
        float cd[WARPS * KNN];
        int   ci[WARPS * KNN];
#pragma unroll
        for (int j = 0; j < WARPS * KNN; j++) {
            cd[j] = s_cd[ms][j];
            ci[j] = s_ci[ms][j];
        }
#pragma unroll
        for (int k = 0; k < KNN; k++) {
            int best = 0;
#pragma unroll
            for (int j = 1; j < WARPS * KNN; j++) {
                // lexicographic (dist, idx): matches top_k tie-break
                if (cd[j] < cd[best] || (cd[j] == cd[best] && ci[j] < ci[best]))
                    best = j;
            }
            s_idx[ms][k] = ci[best];
            cd[best] = 3.4e38f;
        }
    }
    __syncthreads();

    // ---- phase B: warp-cooperative apply ----
    // lane = (prow = lane>>3 in 0..3, e4 = lane&7): covers d in {prow, prow+4, ...}
    // and output columns [4*e4, 4*e4+4).
    const int prow = lane >> 3;
    const int e4   = lane & 7;
    const float4* offs4 = (const float4*)offs;

    for (int sb = w; sb < SPB; sb += WARPS) {
        float4 acc = make_float4(0.f, 0.f, 0.f, 0.f);
#pragma unroll
        for (int k = 0; k < KNN; k++) {
            int f = s_idx[sb][k];
            const float4* w4 = (const float4*)(wts + (size_t)f * D * D);
            const float*  cf = ctrs + (size_t)f * D;
#pragma unroll
            for (int dd = 0; dd < 8; dd++) {
                int d = dd * 4 + prow;
                float4 wv = __ldg(w4 + d * 8 + e4);
                float  xc = s_x[sb * (D + 1) + d] - __ldg(cf + d);
                acc.x = fmaf(xc, wv.x, acc.x);
                acc.y = fmaf(xc, wv.y, acc.y);
                acc.z = fmaf(xc, wv.z, acc.z);
                acc.w = fmaf(xc, wv.w, acc.w);
            }
        }
#pragma unroll
        for (int off = 8; off < 32; off <<= 1) {
            acc.x += __shfl_xor_sync(0xffffffffu, acc.x, off);
            acc.y += __shfl_xor_sync(0xffffffffu, acc.y, off);
            acc.z += __shfl_xor_sync(0xffffffffu, acc.z, off);
            acc.w += __shfl_xor_sync(0xffffffffu, acc.w, off);
        }
        if (prow == 0) {
#pragma unroll
            for (int k = 0; k < KNN; k++) {
                int f = s_idx[sb][k];
                float4 ov = __ldg(offs4 + f * 8 + e4);
                acc.x += ov.x; acc.y += ov.y; acc.z += ov.z; acc.w += ov.w;
            }
            ((float4*)(y + (size_t)(blockIdx.x * SPB + sb) * D))[e4] = acc;
        }
    }
}

// ---------------- launch (ONE kernel) ----------------
extern "C" void kernel_launch(void* const* d_in, const int* in_sizes, int n_in,
                              void* d_out, int out_size)
{
    const float* x    = (const float*)d_in[0];
    const float* ctrs = (const float*)d_in[1];
    const float* wts  = (const float*)d_in[2];
    const float* offs = (const float*)d_in[3];
    float* y = (float*)d_out;

    int n_smps = in_sizes[0] / D;
    int n_fcns = in_sizes[1] / D;

    pwl_kernel<<<n_smps / SPB, 192>>>(x, ctrs, wts, offs, y, n_fcns);
}

// round 17
// speedup vs baseline: 1.2502x; 1.0372x over previous
#include <cuda_runtime.h>

typedef unsigned long long u64;

#define D      32
#define KNN    4
#define WARPS  6
#define SPB    64        // samples per block; lane owns (lane, lane+32)
#define TILE   32

// ---------------- packed f32x2 helpers (sm_103a FFMA2 path) ----------------
__device__ __forceinline__ u64 fma2(u64 a, u64 b, u64 c) {
    u64 r;
    asm("fma.rn.f32x2 %0, %1, %2, %3;" : "=l"(r) : "l"(a), "l"(b), "l"(c));
    return r;
}
__device__ __forceinline__ u64 add2(u64 a, u64 b) {
    u64 r;
    asm("add.rn.f32x2 %0, %1, %2;" : "=l"(r) : "l"(a), "l"(b));
    return r;
}
__device__ __forceinline__ void unpack2(u64 a, float& lo, float& hi) {
    asm("mov.b64 {%0, %1}, %2;" : "=f"(lo), "=f"(hi) : "l"(a));
}
__device__ __forceinline__ u64 pack2(float a, float b) {
    u64 r;
    asm("mov.b64 %0, {%1, %2};" : "=l"(r) : "f"(a), "f"(b));
    return r;
}

// select-only stable top-4 insert; SAFE when sc >= d3 (no-op). Strict <.
#define INS4(sc, f, d0, d1, d2, d3, i0, i1, i2, i3) do {                        \
    bool h0 = (sc) < d0, h1 = (sc) < d1, h2 = (sc) < d2, h3 = (sc) < d3;        \
    float n3 = h3 ? (h2 ? d2 : (sc)) : d3;  int m3 = h3 ? (h2 ? i2 : (f)) : i3; \
    float n2 = h2 ? (h1 ? d1 : (sc)) : d2;  int m2 = h2 ? (h1 ? i1 : (f)) : i2; \
    float n1 = h1 ? (h0 ? d0 : (sc)) : d1;  int m1 = h1 ? (h0 ? i0 : (f)) : i1; \
    d0 = h0 ? (sc) : d0;                    i0 = h0 ? (f) : i0;                 \
    d1 = n1; i1 = m1; d2 = n2; i2 = m2; d3 = n3; i3 = m3;                       \
} while (0)

// per-sample score: 2 chains of 8 fma2, p0 seeded with (cnorm, 0). Exact
// summation order of the R10 champion (rel_err 1.875776e-07).
#define DOT2(xp, cnp, out) do {                                                 \
    u64 p0 = (cnp), p1 = 0ull;                                                  \
    p0 = fma2((xp)[0],  cc[0],  p0);  p1 = fma2((xp)[1],  cc[1],  p1);          \
    p0 = fma2((xp)[2],  cc[2],  p0);  p1 = fma2((xp)[3],  cc[3],  p1);          \
    p0 = fma2((xp)[4],  cc[4],  p0);  p1 = fma2((xp)[5],  cc[5],  p1);          \
    p0 = fma2((xp)[6],  cc[6],  p0);  p1 = fma2((xp)[7],  cc[7],  p1);          \
    p0 = fma2((xp)[8],  cc[8],  p0);  p1 = fma2((xp)[9],  cc[9],  p1);          \
    p0 = fma2((xp)[10], cc[10], p0);  p1 = fma2((xp)[11], cc[11], p1);          \
    p0 = fma2((xp)[12], cc[12], p0);  p1 = fma2((xp)[13], cc[13], p1);          \
    p0 = fma2((xp)[14], cc[14], p0);  p1 = fma2((xp)[15], cc[15], p1);          \
    u64 rr = add2(p0, p1);                                                      \
    float lo, hi; unpack2(rr, lo, hi);                                          \
    (out) = lo + hi;                                                            \
} while (0)

// ---------------- single fused kernel ----------------
// Block = 192 threads = 6 warps, 64 samples. Lane owns samples lane & lane+32,
// so every center broadcast (8x LDS.128 + cnorm) serves 64 sample-pairs.
// Center norms computed INLINE during tile staging via shfl butterfly.
// Warp w scans a tile-granular shard (11/11/11/11/10/10 tiles of 32).
// Merge 24 -> 4 per sample, then the warp-cooperative apply writes y.
// ONE kernel, ONE graph node.
__global__ __launch_bounds__(192, 2) void pwl_kernel(
    const float* __restrict__ x,
    const float* __restrict__ ctrs,
    const float* __restrict__ wts,
    const float* __restrict__ offs,
    float* __restrict__ y,
    int n_fcns)
{
    __shared__ __align__(16) float s_ctr[WARPS][TILE * D];   // 24 KB
    __shared__ float s_cn[WARPS][TILE];
    __shared__ float s_x[SPB * (D + 1)];
    __shared__ float s_cd[SPB][WARPS * KNN];
    __shared__ int   s_ci[SPB][WARPS * KNN];
    __shared__ int   s_idx[SPB][KNN];

    const int lane = threadIdx.x & 31;
    const int w    = threadIdx.x >> 5;
    const int rowA = blockIdx.x * SPB + lane;
    const int rowB = rowA + 32;

    // ---- load both sample rows: registers hold packed (-2*x); warp 0 -> smem ----
    u64 xpA[16], xpB[16];
    {
        const float4* ga = (const float4*)(x + (size_t)rowA * D);
        const float4* gb = (const float4*)(x + (size_t)rowB * D);
#pragma unroll
        for (int j = 0; j < 8; j++) {
            float4 qa = __ldg(ga + j);
            float4 qb = __ldg(gb + j);
            if (w == 0) {
                float* da = s_x + lane * (D + 1) + 4 * j;
                float* db = s_x + (lane + 32) * (D + 1) + 4 * j;
                da[0] = qa.x; da[1] = qa.y; da[2] = qa.z; da[3] = qa.w;
                db[0] = qb.x; db[1] = qb.y; db[2] = qb.z; db[3] = qb.w;
            }
            xpA[2 * j]     = pack2(-2.0f * qa.x, -2.0f * qa.y);
            xpA[2 * j + 1] = pack2(-2.0f * qa.z, -2.0f * qa.w);
            xpB[2 * j]     = pack2(-2.0f * qb.x, -2.0f * qb.y);
            xpB[2 * j + 1] = pack2(-2.0f * qb.z, -2.0f * qb.w);
        }
    }

    // ---- tile-granular shard: warps 0-3 get 11 tiles, warps 4-5 get 10 ----
    const int tb = (w < 4) ? w * 11 : 44 + (w - 4) * 10;
    const int te = tb + ((w < 4) ? 11 : 10);

    float A0 = 3.4e38f, A1 = 3.4e38f, A2 = 3.4e38f, A3 = 3.4e38f;
    float B0 = 3.4e38f, B1 = 3.4e38f, B2 = 3.4e38f, B3 = 3.4e38f;
    int   Ai0 = 0, Ai1 = 0, Ai2 = 0, Ai3 = 0;
    int   Bi0 = 0, Bi1 = 0, Bi2 = 0, Bi3 = 0;

    const float4* cg4 = (const float4*)ctrs;

    for (int tt = tb; tt < te; tt++) {
        const int t = tt * TILE;
        __syncwarp();
        // stage 32 centers for this warp + inline cnorm via shfl butterfly.
        // e = i*32+lane: center t + i*4 + (lane>>3), 16B-chunk (lane&7).
        // Lanes 8g..8g+7 hold the 8 chunks of one center -> reduce with
        // shfl_xor {1,2,4}; lane&7==0 writes s_cn.
#pragma unroll
        for (int i = 0; i < 8; i++) {
            int e = i * 32 + lane;                             // 0..255
            float4 q = __ldg(cg4 + (size_t)(t + (e >> 3)) * 8 + (e & 7));
            ((float4*)s_ctr[w])[e] = q;
            float p = q.x * q.x + q.y * q.y + q.z * q.z + q.w * q.w;
            p += __shfl_xor_sync(0xffffffffu, p, 1);
            p += __shfl_xor_sync(0xffffffffu, p, 2);
            p += __shfl_xor_sync(0xffffffffu, p, 4);
            if ((lane & 7) == 0)
                s_cn[w][i * 4 + (lane >> 3)] = p;
        }
        __syncwarp();

#pragma unroll 4
        for (int ff = 0; ff < TILE; ff++) {
            const u64* cc = (const u64*)(s_ctr[w] + ff * D);   // 16 packed pairs
            u64 cnp = (u64)__float_as_uint(s_cn[w][ff]);       // (cnorm, 0)
            float scA, scB;                    // == cnorm - 2*dot (rank-equiv)
            DOT2(xpA, cnp, scA);
            DOT2(xpB, cnp, scB);
            const int f = t + ff;
            if (scA < A3 || scB < B3) {        // rare after warmup
                INS4(scA, f, A0, A1, A2, A3, Ai0, Ai1, Ai2, Ai3);
                INS4(scB, f, B0, B1, B2, B3, Bi0, Bi1, Bi2, Bi3);
            }
        }
    }

    // ---- publish candidates, merge 24 -> 4 per sample ----
    s_cd[lane][w * KNN + 0] = A0;       s_ci[lane][w * KNN + 0] = Ai0;
    s_cd[lane][w * KNN + 1] = A1;       s_ci[lane][w * KNN + 1] = Ai1;
    s_cd[lane][w * KNN + 2] = A2;       s_ci[lane][w * KNN + 2] = Ai2;
    s_cd[lane][w * KNN + 3] = A3;       s_ci[lane][w * KNN + 3] = Ai3;
    s_cd[lane + 32][w * KNN + 0] = B0;  s_ci[lane + 32][w * KNN + 0] = Bi0;
    s_cd[lane + 32][w * KNN + 1] = B1;  s_ci[lane + 32][w * KNN + 1] = Bi1;
    s_cd[lane + 32][w * KNN + 2] = B2;  s_ci[lane + 32][w * KNN + 2] = Bi2;
    s_cd[lane + 32][w * KNN + 3] = B3;  s_ci[lane + 32][w * KNN + 3] = Bi3;
    __syncthreads();

    if (threadIdx.x < SPB) {
        const int ms = threadIdx.x;
        float cd[WARPS * KNN];
        int   ci[WARPS * KNN];
#pragma unroll
        for (int j = 0; j < WARPS * KNN; j++) {
            cd[j] = s_cd[ms][j];
            ci[j] = s_ci[ms][j];
        }
#pragma unroll
        for (int k = 0; k < KNN; k++) {
            int best = 0;
#pragma unroll
            for (int j = 1; j < WARPS * KNN; j++) {
                // lexicographic (dist, idx): matches top_k tie-break
                if (cd[j] < cd[best] || (cd[j] == cd[best] && ci[j] < ci[best]))
                    best = j;
            }
            s_idx[ms][k] = ci[best];
            cd[best] = 3.4e38f;
        }
    }
    __syncthreads();

    // ---- phase B: warp-cooperative apply ----
    // lane = (prow = lane>>3 in 0..3, e4 = lane&7): covers d in {prow, prow+4, ...}
    // and output columns [4*e4, 4*e4+4).
    const int prow = lane >> 3;
    const int e4   = lane & 7;
    const float4* offs4 = (const float4*)offs;

    for (int sb = w; sb < SPB; sb += WARPS) {
        float4 acc = make_float4(0.f, 0.f, 0.f, 0.f);
#pragma unroll
        for (int k = 0; k < KNN; k++) {
            int f = s_idx[sb][k];
            const float4* w4 = (const float4*)(wts + (size_t)f * D * D);
            const float*  cf = ctrs + (size_t)f * D;
#pragma unroll
            for (int dd = 0; dd < 8; dd++) {
                int d = dd * 4 + prow;
                float4 wv = __ldg(w4 + d * 8 + e4);
                float  xc = s_x[sb * (D + 1) + d] - __ldg(cf + d);
                acc.x = fmaf(xc, wv.x, acc.x);
                acc.y = fmaf(xc, wv.y, acc.y);
                acc.z = fmaf(xc, wv.z, acc.z);
                acc.w = fmaf(xc, wv.w, acc.w);
            }
        }
#pragma unroll
        for (int off = 8; off < 32; off <<= 1) {
            acc.x += __shfl_xor_sync(0xffffffffu, acc.x, off);
            acc.y += __shfl_xor_sync(0xffffffffu, acc.y, off);
            acc.z += __shfl_xor_sync(0xffffffffu, acc.z, off);
            acc.w += __shfl_xor_sync(0xffffffffu, acc.w, off);
        }
        if (prow == 0) {
#pragma unroll
            for (int k = 0; k < KNN; k++) {
                int f = s_idx[sb][k];
                float4 ov = __ldg(offs4 + f * 8 + e4);
                acc.x += ov.x; acc.y += ov.y; acc.z += ov.z; acc.w += ov.w;
            }
            ((float4*)(y + (size_t)(blockIdx.x * SPB + sb) * D))[e4] = acc;
        }
    }
}

// ---------------- launch (ONE kernel) ----------------
extern "C" void kernel_launch(void* const* d_in, const int* in_sizes, int n_in,
                              void* d_out, int out_size)
{
    const float* x    = (const float*)d_in[0];
    const float* ctrs = (const float*)d_in[1];
    const float* wts  = (const float*)d_in[2];
    const float* offs = (const float*)d_in[3];
    float* y = (float*)d_out;

    int n_smps = in_sizes[0] / D;
    int n_fcns = in_sizes[1] / D;

    pwl_kernel<<<n_smps / SPB, 192>>>(x, ctrs, wts, offs, y, n_fcns);
}